// round 1
// baseline (speedup 1.0000x reference)
#include <cuda_runtime.h>
#include <math.h>

#define VOCAB 32000
#define EMB   256
#define UNITS 1024
#define NB    64     // batch
#define NT    256    // time steps
#define G3    3072   // 3*UNITS

// ---------------- scratch (static device allocations are the sanctioned path) ----
__device__ float g_gx[(size_t)2 * NT * NB * G3];   // packed gate-major inputs, ~402 MB
__device__ float g_W [(size_t)2 * EMB * G3];       // packed input weights
__device__ float g_U [(size_t)2 * UNITS * G3];     // packed recurrent weights
__device__ float g_h [2][2][NB][UNITS];            // [dir][pingpong][b][u]
__device__ unsigned char g_mask[2][NT][NB];
__device__ unsigned g_bar_count;
__device__ unsigned g_bar_gen;

// ---------------- grid barrier (sense via monotonically increasing generation) ---
__device__ __forceinline__ void grid_barrier(unsigned nblk, unsigned target) {
    __syncthreads();
    if (threadIdx.x == 0) {
        __threadfence();
        unsigned arrived = atomicAdd(&g_bar_count, 1u);
        if (arrived == nblk - 1u) {
            g_bar_count = 0u;
            __threadfence();
            atomicExch(&g_bar_gen, target);
        } else {
            volatile unsigned* gen = &g_bar_gen;
            while (*gen < target) { }
            __threadfence();
        }
    }
    __syncthreads();
}

// ---------------- prep: pack U/W to unit-major gate layout, masks, h init --------
__global__ void prep_kernel(const int* __restrict__ x, const float* __restrict__ hidden,
                            const float* __restrict__ Wf, const float* __restrict__ Uf,
                            const float* __restrict__ Wb, const float* __restrict__ Ub) {
    const long long NU = 2LL * UNITS * G3;
    const long long NW = 2LL * EMB * G3;
    const long long NM = 2LL * NT * NB;
    const long long NH = 2LL * NB * UNITS;
    const long long total = NU + NW + NM + NH;
    const long long stride = (long long)gridDim.x * blockDim.x;
    for (long long i = (long long)blockIdx.x * blockDim.x + threadIdx.x; i < total; i += stride) {
        if (i < NU) {
            long long dir = i / ((long long)UNITS * G3);
            long long rem = i - dir * (long long)UNITS * G3;
            int k = (int)(rem / G3);
            int p = (int)(rem % G3);
            const float* U = dir ? Ub : Uf;
            g_U[i] = U[(long long)k * G3 + (p % 3) * UNITS + p / 3];
        } else if (i < NU + NW) {
            long long j = i - NU;
            long long dir = j / ((long long)EMB * G3);
            long long rem = j - dir * (long long)EMB * G3;
            int k = (int)(rem / G3);
            int p = (int)(rem % G3);
            const float* W = dir ? Wb : Wf;
            g_W[j] = W[(long long)k * G3 + (p % 3) * UNITS + p / 3];
        } else if (i < NU + NW + NM) {
            long long j = i - NU - NW;
            int dir = (int)(j / (NT * NB));
            int rem = (int)(j % (NT * NB));
            int s = rem / NB, b = rem % NB;
            int t = dir ? (NT - 1 - s) : s;
            g_mask[dir][s][b] = (x[b * NT + t] != 0) ? 1 : 0;
        } else {
            long long j = i - NU - NW - NM;
            int dir = (int)(j / (NB * UNITS));
            int rem = (int)(j % (NB * UNITS));
            g_h[dir][0][rem / UNITS][rem % UNITS] = hidden[rem];
        }
    }
    if (blockIdx.x == 0 && threadIdx.x == 0) { g_bar_count = 0u; g_bar_gen = 0u; }
}

// ---------------- gx = gather(emb, x) @ W_packed + b_in  (per dir, per t) --------
// grid: (48 col-tiles, NT, 2 dirs), block 256. Tile 64x64, K=256 in chunks of 16.
__global__ __launch_bounds__(256) void gx_kernel(const int* __restrict__ x,
                                                 const float* __restrict__ emb,
                                                 const float* __restrict__ bf_in,
                                                 const float* __restrict__ bb_in) {
    const int ct  = blockIdx.x;     // column tile (64 packed cols)
    const int t   = blockIdx.y;     // step index within this direction's order
    const int dir = blockIdx.z;
    const int tid = threadIdx.x;
    const int pbase = ct * 64;
    const int tx = tid & 15, ty = tid >> 4;

    __shared__ float As[16][68];
    __shared__ float Ws[16][68];
    __shared__ int   toks[64];

    if (tid < 64) {
        int tt = dir ? (NT - 1 - t) : t;
        toks[tid] = x[tid * NT + tt];
    }
    __syncthreads();

    const float* Wsrc = g_W + (size_t)dir * EMB * G3;
    float acc[4][4];
#pragma unroll
    for (int i = 0; i < 4; i++)
#pragma unroll
        for (int j = 0; j < 4; j++) acc[i][j] = 0.f;

    for (int k0 = 0; k0 < EMB; k0 += 16) {
        {   // A tile: 64 rows (batch) x 16 k, gathered from emb
            int r   = tid >> 2;
            int kk4 = (tid & 3) << 2;
            const float4 v = *(const float4*)(emb + (size_t)toks[r] * EMB + k0 + kk4);
            As[kk4 + 0][r] = v.x; As[kk4 + 1][r] = v.y;
            As[kk4 + 2][r] = v.z; As[kk4 + 3][r] = v.w;
        }
        {   // W tile: 16 k x 64 packed cols
            int kk = tid >> 4;
            int p4 = (tid & 15) << 2;
            *(float4*)&Ws[kk][p4] = *(const float4*)(Wsrc + (size_t)(k0 + kk) * G3 + pbase + p4);
        }
        __syncthreads();
#pragma unroll
        for (int kk = 0; kk < 16; kk++) {
            float4 a = *(const float4*)&As[kk][ty << 2];
            float4 w = *(const float4*)&Ws[kk][tx << 2];
            acc[0][0] = fmaf(a.x, w.x, acc[0][0]); acc[0][1] = fmaf(a.x, w.y, acc[0][1]);
            acc[0][2] = fmaf(a.x, w.z, acc[0][2]); acc[0][3] = fmaf(a.x, w.w, acc[0][3]);
            acc[1][0] = fmaf(a.y, w.x, acc[1][0]); acc[1][1] = fmaf(a.y, w.y, acc[1][1]);
            acc[1][2] = fmaf(a.y, w.z, acc[1][2]); acc[1][3] = fmaf(a.y, w.w, acc[1][3]);
            acc[2][0] = fmaf(a.z, w.x, acc[2][0]); acc[2][1] = fmaf(a.z, w.y, acc[2][1]);
            acc[2][2] = fmaf(a.z, w.z, acc[2][2]); acc[2][3] = fmaf(a.z, w.w, acc[2][3]);
            acc[3][0] = fmaf(a.w, w.x, acc[3][0]); acc[3][1] = fmaf(a.w, w.y, acc[3][1]);
            acc[3][2] = fmaf(a.w, w.z, acc[3][2]); acc[3][3] = fmaf(a.w, w.w, acc[3][3]);
        }
        __syncthreads();
    }

    // epilogue: + b_in (original gate-major layout), write packed gx
    const float* bsrc = dir ? bb_in : bf_in;
    float bin[4];
#pragma unroll
    for (int j = 0; j < 4; j++) {
        int p = pbase + (tx << 2) + j;
        bin[j] = bsrc[(p % 3) * UNITS + p / 3];
    }
    float* gxbase = g_gx + ((size_t)(dir * NT + t) * NB) * G3;
#pragma unroll
    for (int i = 0; i < 4; i++) {
        int b = (ty << 2) + i;
        float4 o = make_float4(acc[i][0] + bin[0], acc[i][1] + bin[1],
                               acc[i][2] + bin[2], acc[i][3] + bin[3]);
        *(float4*)(gxbase + (size_t)b * G3 + pbase + (tx << 2)) = o;
    }
}

// ---------------- persistent recurrent kernel: both directions, 256 steps --------
// 128 blocks = 2 dirs x 64 unit-tiles (16 units = 48 packed cols each), 256 thr.
// Per step: 64x48x1024 fp32 GEMM + GRU gate update for 16 units x 64 batch.
#define REC_BLOCKS 128
__global__ __launch_bounds__(256) void recurrent_kernel(const float* __restrict__ bf_rec,
                                                        const float* __restrict__ bb_rec,
                                                        float* __restrict__ out) {
    const int blk   = blockIdx.x;
    const int dir   = blk >> 6;
    const int utile = blk & 63;
    const int pbase = utile * 48;
    const int ubase = utile * 16;
    const int tid = threadIdx.x;
    const int tx = tid & 15;      // unit within tile
    const int ty = tid >> 4;      // row group (4 batch rows)
    const int u  = ubase + tx;

    const float* brec = dir ? bb_rec : bf_rec;
    const float bz = brec[u];
    const float br = brec[UNITS + u];
    const float bh = brec[2 * UNITS + u];

    const float* Up = g_U + (size_t)dir * UNITS * G3;
    const unsigned char* msk = &g_mask[dir][0][0];

    __shared__ float hs[16][68];
    __shared__ float us[16][48];

    for (int s = 0; s < NT; s++) {
        const float* hcur = &g_h[dir][s & 1][0][0];
        float*       hnxt = &g_h[dir][(s + 1) & 1][0][0];

        float acc[4][3];
#pragma unroll
        for (int i = 0; i < 4; i++) { acc[i][0] = 0.f; acc[i][1] = 0.f; acc[i][2] = 0.f; }

        for (int k0 = 0; k0 < UNITS; k0 += 16) {
            {   // h tile (L2 load — h is written by other SMs, L1 not coherent)
                int b   = tid >> 2;
                int kk4 = (tid & 3) << 2;
                float4 v = __ldcg((const float4*)(hcur + (size_t)b * UNITS + k0 + kk4));
                hs[kk4 + 0][b] = v.x; hs[kk4 + 1][b] = v.y;
                hs[kk4 + 2][b] = v.z; hs[kk4 + 3][b] = v.w;
            }
            if (tid < 192) {   // U tile 16 x 48
                int kk = tid / 12;
                int p4 = (tid % 12) << 2;
                *(float4*)&us[kk][p4] = *(const float4*)(Up + (size_t)(k0 + kk) * G3 + pbase + p4);
            }
            __syncthreads();
#pragma unroll
            for (int kk = 0; kk < 16; kk++) {
                float4 h4 = *(const float4*)&hs[kk][ty << 2];
                float u0 = us[kk][tx * 3 + 0];
                float u1 = us[kk][tx * 3 + 1];
                float u2 = us[kk][tx * 3 + 2];
                acc[0][0] = fmaf(h4.x, u0, acc[0][0]); acc[0][1] = fmaf(h4.x, u1, acc[0][1]); acc[0][2] = fmaf(h4.x, u2, acc[0][2]);
                acc[1][0] = fmaf(h4.y, u0, acc[1][0]); acc[1][1] = fmaf(h4.y, u1, acc[1][1]); acc[1][2] = fmaf(h4.y, u2, acc[1][2]);
                acc[2][0] = fmaf(h4.z, u0, acc[2][0]); acc[2][1] = fmaf(h4.z, u1, acc[2][1]); acc[2][2] = fmaf(h4.z, u2, acc[2][2]);
                acc[3][0] = fmaf(h4.w, u0, acc[3][0]); acc[3][1] = fmaf(h4.w, u1, acc[3][1]); acc[3][2] = fmaf(h4.w, u2, acc[3][2]);
            }
            __syncthreads();
        }

        // GRU update for this thread's unit u, 4 batch rows
        const float* gxp = g_gx + ((size_t)(dir * NT + s) * NB) * G3;
        const int tt = dir ? (NT - 1 - s) : s;
#pragma unroll
        for (int i = 0; i < 4; i++) {
            int b = (ty << 2) + i;
            const float* gx = gxp + (size_t)b * G3 + pbase + tx * 3;
            float xz = gx[0], xr = gx[1], xh = gx[2];
            float z  = 1.f / (1.f + expf(-(xz + acc[i][0] + bz)));
            float r  = 1.f / (1.f + expf(-(xr + acc[i][1] + br)));
            float hh = tanhf(xh + r * (acc[i][2] + bh));
            float hp = __ldcg(hcur + (size_t)b * UNITS + u);
            float hn = z * hp + (1.f - z) * hh;
            if (!msk[s * NB + b]) hn = hp;
            hnxt[(size_t)b * UNITS + u] = hn;
            out[((size_t)b * NT + tt) * (2 * UNITS) + dir * UNITS + u] = hn;
        }
        __threadfence();
        grid_barrier(gridDim.x, (unsigned)(s + 1));
    }
}

// ---------------- final state: tanh(concat(hf,hb) @ Wp + bp) ---------------------
__global__ __launch_bounds__(256) void state_kernel(const float* __restrict__ Wp,
                                                    const float* __restrict__ bp,
                                                    float* __restrict__ out) {
    const int b = blockIdx.x;
    const int tid = threadIdx.x;
    __shared__ float hcat[2 * UNITS];
    for (int k = tid; k < UNITS; k += 256) {
        hcat[k]         = g_h[0][0][b][k];   // NT even -> final h in buffer 0
        hcat[UNITS + k] = g_h[1][0][b][k];
    }
    __syncthreads();
    const int u4 = tid * 4;
    float4 acc = make_float4(0.f, 0.f, 0.f, 0.f);
    for (int k = 0; k < 2 * UNITS; k++) {
        float4 w = __ldg((const float4*)(Wp + (size_t)k * UNITS + u4));
        float h = hcat[k];
        acc.x = fmaf(h, w.x, acc.x); acc.y = fmaf(h, w.y, acc.y);
        acc.z = fmaf(h, w.z, acc.z); acc.w = fmaf(h, w.w, acc.w);
    }
    float4 bb4 = *(const float4*)(bp + u4);
    const size_t off = (size_t)NB * NT * (2 * UNITS) + (size_t)b * UNITS + u4;
    out[off + 0] = tanhf(acc.x + bb4.x);
    out[off + 1] = tanhf(acc.y + bb4.y);
    out[off + 2] = tanhf(acc.z + bb4.z);
    out[off + 3] = tanhf(acc.w + bb4.w);
}

// ---------------- launch ----------------------------------------------------------
extern "C" void kernel_launch(void* const* d_in, const int* in_sizes, int n_in,
                              void* d_out, int out_size) {
    (void)in_sizes; (void)n_in; (void)out_size;
    const int*   x      = (const int*)  d_in[0];
    const float* hidden = (const float*)d_in[1];
    const float* emb    = (const float*)d_in[2];
    const float* Wf     = (const float*)d_in[3];
    const float* Uf     = (const float*)d_in[4];
    const float* bf_in  = (const float*)d_in[5];
    const float* bf_rec = (const float*)d_in[6];
    const float* Wb     = (const float*)d_in[7];
    const float* Ub     = (const float*)d_in[8];
    const float* bb_in  = (const float*)d_in[9];
    const float* bb_rec = (const float*)d_in[10];
    const float* Wp     = (const float*)d_in[11];
    const float* bp     = (const float*)d_in[12];
    float* out = (float*)d_out;

    prep_kernel<<<4096, 256>>>(x, hidden, Wf, Uf, Wb, Ub);
    dim3 ggx(G3 / 64, NT, 2);
    gx_kernel<<<ggx, 256>>>(x, emb, bf_in, bb_in);
    recurrent_kernel<<<REC_BLOCKS, 256>>>(bf_rec, bb_rec, out);
    state_kernel<<<NB, 256>>>(Wp, bp, out);
}

// round 2
// speedup vs baseline: 1.0683x; 1.0683x over previous
#include <cuda_runtime.h>
#include <math.h>

#define VOCAB 32000
#define EMB   256
#define UNITS 1024
#define NB    64     // batch
#define NT    256    // time steps
#define G3    3072   // 3*UNITS

// ---------------- scratch (static device allocations are the sanctioned path) ----
__device__ float g_gx[(size_t)2 * NT * NB * G3];   // packed gate-major inputs, ~402 MB
__device__ float g_W [(size_t)2 * EMB * G3];       // packed input weights
__device__ float g_U [(size_t)2 * UNITS * G3];     // packed recurrent weights
__device__ float g_h [2][2][NB][UNITS];            // [dir][pingpong][b][u]
__device__ unsigned char g_mask[2][NT][NB];
__device__ unsigned g_bar_count;
__device__ unsigned g_bar_gen;

// ---------------- grid barrier (sense via monotonically increasing generation) ---
__device__ __forceinline__ void grid_barrier(unsigned nblk, unsigned target) {
    __syncthreads();
    if (threadIdx.x == 0) {
        __threadfence();
        unsigned arrived = atomicAdd(&g_bar_count, 1u);
        if (arrived == nblk - 1u) {
            g_bar_count = 0u;
            __threadfence();
            atomicExch(&g_bar_gen, target);
        } else {
            volatile unsigned* gen = &g_bar_gen;
            while (*gen < target) { }
            __threadfence();
        }
    }
    __syncthreads();
}

// ---------------- prep: pack U/W to unit-major gate layout, masks, h init --------
__global__ void prep_kernel(const int* __restrict__ x, const float* __restrict__ hidden,
                            const float* __restrict__ Wf, const float* __restrict__ Uf,
                            const float* __restrict__ Wb, const float* __restrict__ Ub) {
    const long long NU = 2LL * UNITS * G3;
    const long long NW = 2LL * EMB * G3;
    const long long NM = 2LL * NT * NB;
    const long long NH = 2LL * NB * UNITS;
    const long long total = NU + NW + NM + NH;
    const long long stride = (long long)gridDim.x * blockDim.x;
    for (long long i = (long long)blockIdx.x * blockDim.x + threadIdx.x; i < total; i += stride) {
        if (i < NU) {
            long long dir = i / ((long long)UNITS * G3);
            long long rem = i - dir * (long long)UNITS * G3;
            int k = (int)(rem / G3);
            int p = (int)(rem % G3);
            const float* U = dir ? Ub : Uf;
            g_U[i] = U[(long long)k * G3 + (p % 3) * UNITS + p / 3];
        } else if (i < NU + NW) {
            long long j = i - NU;
            long long dir = j / ((long long)EMB * G3);
            long long rem = j - dir * (long long)EMB * G3;
            int k = (int)(rem / G3);
            int p = (int)(rem % G3);
            const float* W = dir ? Wb : Wf;
            g_W[j] = W[(long long)k * G3 + (p % 3) * UNITS + p / 3];
        } else if (i < NU + NW + NM) {
            long long j = i - NU - NW;
            int dir = (int)(j / (NT * NB));
            int rem = (int)(j % (NT * NB));
            int s = rem / NB, b = rem % NB;
            int t = dir ? (NT - 1 - s) : s;
            g_mask[dir][s][b] = (x[b * NT + t] != 0) ? 1 : 0;
        } else {
            long long j = i - NU - NW - NM;
            int dir = (int)(j / (NB * UNITS));
            int rem = (int)(j % (NB * UNITS));
            g_h[dir][0][rem / UNITS][rem % UNITS] = hidden[rem];
        }
    }
    if (blockIdx.x == 0 && threadIdx.x == 0) { g_bar_count = 0u; g_bar_gen = 0u; }
}

// ---------------- gx = gather(emb, x) @ W_packed + b_in  (per dir, per t) --------
// grid: (48 col-tiles, NT, 2 dirs), block 256. Tile 64x64, K=256 in chunks of 16.
__global__ __launch_bounds__(256) void gx_kernel(const int* __restrict__ x,
                                                 const float* __restrict__ emb,
                                                 const float* __restrict__ bf_in,
                                                 const float* __restrict__ bb_in) {
    const int ct  = blockIdx.x;     // column tile (64 packed cols)
    const int t   = blockIdx.y;     // step index within this direction's order
    const int dir = blockIdx.z;
    const int tid = threadIdx.x;
    const int pbase = ct * 64;
    const int tx = tid & 15, ty = tid >> 4;

    __shared__ float As[16][68];
    __shared__ float Ws[16][68];
    __shared__ int   toks[64];

    if (tid < 64) {
        int tt = dir ? (NT - 1 - t) : t;
        toks[tid] = x[tid * NT + tt];
    }
    __syncthreads();

    const float* Wsrc = g_W + (size_t)dir * EMB * G3;
    float acc[4][4];
#pragma unroll
    for (int i = 0; i < 4; i++)
#pragma unroll
        for (int j = 0; j < 4; j++) acc[i][j] = 0.f;

    for (int k0 = 0; k0 < EMB; k0 += 16) {
        {   // A tile: 64 rows (batch) x 16 k, gathered from emb
            int r   = tid >> 2;
            int kk4 = (tid & 3) << 2;
            const float4 v = *(const float4*)(emb + (size_t)toks[r] * EMB + k0 + kk4);
            As[kk4 + 0][r] = v.x; As[kk4 + 1][r] = v.y;
            As[kk4 + 2][r] = v.z; As[kk4 + 3][r] = v.w;
        }
        {   // W tile: 16 k x 64 packed cols
            int kk = tid >> 4;
            int p4 = (tid & 15) << 2;
            *(float4*)&Ws[kk][p4] = *(const float4*)(Wsrc + (size_t)(k0 + kk) * G3 + pbase + p4);
        }
        __syncthreads();
#pragma unroll
        for (int kk = 0; kk < 16; kk++) {
            float4 a = *(const float4*)&As[kk][ty << 2];
            float4 w = *(const float4*)&Ws[kk][tx << 2];
            acc[0][0] = fmaf(a.x, w.x, acc[0][0]); acc[0][1] = fmaf(a.x, w.y, acc[0][1]);
            acc[0][2] = fmaf(a.x, w.z, acc[0][2]); acc[0][3] = fmaf(a.x, w.w, acc[0][3]);
            acc[1][0] = fmaf(a.y, w.x, acc[1][0]); acc[1][1] = fmaf(a.y, w.y, acc[1][1]);
            acc[1][2] = fmaf(a.y, w.z, acc[1][2]); acc[1][3] = fmaf(a.y, w.w, acc[1][3]);
            acc[2][0] = fmaf(a.z, w.x, acc[2][0]); acc[2][1] = fmaf(a.z, w.y, acc[2][1]);
            acc[2][2] = fmaf(a.z, w.z, acc[2][2]); acc[2][3] = fmaf(a.z, w.w, acc[2][3]);
            acc[3][0] = fmaf(a.w, w.x, acc[3][0]); acc[3][1] = fmaf(a.w, w.y, acc[3][1]);
            acc[3][2] = fmaf(a.w, w.z, acc[3][2]); acc[3][3] = fmaf(a.w, w.w, acc[3][3]);
        }
        __syncthreads();
    }

    // epilogue: + b_in (original gate-major layout), write packed gx
    const float* bsrc = dir ? bb_in : bf_in;
    float bin[4];
#pragma unroll
    for (int j = 0; j < 4; j++) {
        int p = pbase + (tx << 2) + j;
        bin[j] = bsrc[(p % 3) * UNITS + p / 3];
    }
    float* gxbase = g_gx + ((size_t)(dir * NT + t) * NB) * G3;
#pragma unroll
    for (int i = 0; i < 4; i++) {
        int b = (ty << 2) + i;
        float4 o = make_float4(acc[i][0] + bin[0], acc[i][1] + bin[1],
                               acc[i][2] + bin[2], acc[i][3] + bin[3]);
        *(float4*)(gxbase + (size_t)b * G3 + pbase + (tx << 2)) = o;
    }
}

// ---------------- persistent recurrent kernel: both directions, 256 steps --------
// 128 blocks = 2 dirs x 64 unit-tiles (16 units = 48 packed cols each), 256 thr.
// Per step: 64x48x1024 fp32 GEMM + GRU gate update for 16 units x 64 batch.
#define REC_BLOCKS 128
__global__ __launch_bounds__(256) void recurrent_kernel(const float* __restrict__ bf_rec,
                                                        const float* __restrict__ bb_rec,
                                                        float* __restrict__ out) {
    const int blk   = blockIdx.x;
    const int dir   = blk >> 6;
    const int utile = blk & 63;
    const int pbase = utile * 48;
    const int ubase = utile * 16;
    const int tid = threadIdx.x;
    const int tx = tid & 15;      // unit within tile
    const int ty = tid >> 4;      // row group (4 batch rows)
    const int u  = ubase + tx;

    const float* brec = dir ? bb_rec : bf_rec;
    const float bz = brec[u];
    const float br = brec[UNITS + u];
    const float bh = brec[2 * UNITS + u];

    const float* Up = g_U + (size_t)dir * UNITS * G3;
    const unsigned char* msk = &g_mask[dir][0][0];

    __shared__ float hs[16][68];
    __shared__ float us[16][48];

    for (int s = 0; s < NT; s++) {
        const float* hcur = &g_h[dir][s & 1][0][0];
        float*       hnxt = &g_h[dir][(s + 1) & 1][0][0];

        float acc[4][3];
#pragma unroll
        for (int i = 0; i < 4; i++) { acc[i][0] = 0.f; acc[i][1] = 0.f; acc[i][2] = 0.f; }

        for (int k0 = 0; k0 < UNITS; k0 += 16) {
            {   // h tile (L2 load — h is written by other SMs, L1 not coherent)
                int b   = tid >> 2;
                int kk4 = (tid & 3) << 2;
                float4 v = __ldcg((const float4*)(hcur + (size_t)b * UNITS + k0 + kk4));
                hs[kk4 + 0][b] = v.x; hs[kk4 + 1][b] = v.y;
                hs[kk4 + 2][b] = v.z; hs[kk4 + 3][b] = v.w;
            }
            if (tid < 192) {   // U tile 16 x 48
                int kk = tid / 12;
                int p4 = (tid % 12) << 2;
                *(float4*)&us[kk][p4] = *(const float4*)(Up + (size_t)(k0 + kk) * G3 + pbase + p4);
            }
            __syncthreads();
#pragma unroll
            for (int kk = 0; kk < 16; kk++) {
                float4 h4 = *(const float4*)&hs[kk][ty << 2];
                float u0 = us[kk][tx * 3 + 0];
                float u1 = us[kk][tx * 3 + 1];
                float u2 = us[kk][tx * 3 + 2];
                acc[0][0] = fmaf(h4.x, u0, acc[0][0]); acc[0][1] = fmaf(h4.x, u1, acc[0][1]); acc[0][2] = fmaf(h4.x, u2, acc[0][2]);
                acc[1][0] = fmaf(h4.y, u0, acc[1][0]); acc[1][1] = fmaf(h4.y, u1, acc[1][1]); acc[1][2] = fmaf(h4.y, u2, acc[1][2]);
                acc[2][0] = fmaf(h4.z, u0, acc[2][0]); acc[2][1] = fmaf(h4.z, u1, acc[2][1]); acc[2][2] = fmaf(h4.z, u2, acc[2][2]);
                acc[3][0] = fmaf(h4.w, u0, acc[3][0]); acc[3][1] = fmaf(h4.w, u1, acc[3][1]); acc[3][2] = fmaf(h4.w, u2, acc[3][2]);
            }
            __syncthreads();
        }

        // GRU update for this thread's unit u, 4 batch rows
        const float* gxp = g_gx + ((size_t)(dir * NT + s) * NB) * G3;
        const int tt = dir ? (NT - 1 - s) : s;
#pragma unroll
        for (int i = 0; i < 4; i++) {
            int b = (ty << 2) + i;
            const float* gx = gxp + (size_t)b * G3 + pbase + tx * 3;
            float xz = gx[0], xr = gx[1], xh = gx[2];
            float z  = 1.f / (1.f + expf(-(xz + acc[i][0] + bz)));
            float r  = 1.f / (1.f + expf(-(xr + acc[i][1] + br)));
            float hh = tanhf(xh + r * (acc[i][2] + bh));
            float hp = __ldcg(hcur + (size_t)b * UNITS + u);
            float hn = z * hp + (1.f - z) * hh;
            if (!msk[s * NB + b]) hn = hp;
            hnxt[(size_t)b * UNITS + u] = hn;
            out[((size_t)b * NT + tt) * (2 * UNITS) + dir * UNITS + u] = hn;
        }
        __threadfence();
        grid_barrier(gridDim.x, (unsigned)(s + 1));
    }
}

// ---------------- final state: tanh(concat(hf,hb) @ Wp + bp) ---------------------
__global__ __launch_bounds__(256) void state_kernel(const float* __restrict__ Wp,
                                                    const float* __restrict__ bp,
                                                    float* __restrict__ out) {
    const int b = blockIdx.x;
    const int tid = threadIdx.x;
    __shared__ float hcat[2 * UNITS];
    for (int k = tid; k < UNITS; k += 256) {
        hcat[k]         = g_h[0][0][b][k];   // NT even -> final h in buffer 0
        hcat[UNITS + k] = g_h[1][0][b][k];
    }
    __syncthreads();
    const int u4 = tid * 4;
    float4 acc = make_float4(0.f, 0.f, 0.f, 0.f);
    for (int k = 0; k < 2 * UNITS; k++) {
        float4 w = __ldg((const float4*)(Wp + (size_t)k * UNITS + u4));
        float h = hcat[k];
        acc.x = fmaf(h, w.x, acc.x); acc.y = fmaf(h, w.y, acc.y);
        acc.z = fmaf(h, w.z, acc.z); acc.w = fmaf(h, w.w, acc.w);
    }
    float4 bb4 = *(const float4*)(bp + u4);
    const size_t off = (size_t)NB * NT * (2 * UNITS) + (size_t)b * UNITS + u4;
    out[off + 0] = tanhf(acc.x + bb4.x);
    out[off + 1] = tanhf(acc.y + bb4.y);
    out[off + 2] = tanhf(acc.z + bb4.z);
    out[off + 3] = tanhf(acc.w + bb4.w);
}

// ---------------- launch ----------------------------------------------------------
extern "C" void kernel_launch(void* const* d_in, const int* in_sizes, int n_in,
                              void* d_out, int out_size) {
    (void)in_sizes; (void)n_in; (void)out_size;
    const int*   x      = (const int*)  d_in[0];
    const float* hidden = (const float*)d_in[1];
    const float* emb    = (const float*)d_in[2];
    const float* Wf     = (const float*)d_in[3];
    const float* Uf     = (const float*)d_in[4];
    const float* bf_in  = (const float*)d_in[5];
    const float* bf_rec = (const float*)d_in[6];
    const float* Wb     = (const float*)d_in[7];
    const float* Ub     = (const float*)d_in[8];
    const float* bb_in  = (const float*)d_in[9];
    const float* bb_rec = (const float*)d_in[10];
    const float* Wp     = (const float*)d_in[11];
    const float* bp     = (const float*)d_in[12];
    float* out = (float*)d_out;

    prep_kernel<<<4096, 256>>>(x, hidden, Wf, Uf, Wb, Ub);
    dim3 ggx(G3 / 64, NT, 2);
    gx_kernel<<<ggx, 256>>>(x, emb, bf_in, bb_in);
    recurrent_kernel<<<REC_BLOCKS, 256>>>(bf_rec, bb_rec, out);
    state_kernel<<<NB, 256>>>(Wp, bp, out);
}

// round 3
// speedup vs baseline: 1.5379x; 1.4395x over previous
#include <cuda_runtime.h>
#include <math.h>

#define VOCAB 32000
#define EMB   256
#define UNITS 1024
#define NB    64     // batch
#define NT    256    // time steps
#define G3    3072   // 3*UNITS
#define REC_BLOCKS 128
#define KC    64     // k-chunk for h staging

// ---------------- scratch ---------------------------------------------------------
__device__ float g_gx[(size_t)2 * NT * NB * G3];   // packed gate-major inputs
__device__ float g_W [(size_t)2 * EMB * G3];       // packed input weights
__device__ float g_U [(size_t)2 * UNITS * G3];     // packed recurrent weights
__device__ float g_h [2][2][UNITS][NB];            // TRANSPOSED: [dir][pingpong][u][b]
__device__ unsigned char g_mask[2][NT][NB];
__device__ unsigned g_bar_count;                   // monotonic arrivals
__device__ unsigned g_bar_gen;                     // released generation

// ---------------- packed f32x2 helpers --------------------------------------------
__device__ __forceinline__ unsigned long long pack2(float x) {
    unsigned long long r;
    asm("mov.b64 %0, {%1, %1};" : "=l"(r) : "f"(x));
    return r;
}
__device__ __forceinline__ void ffma2(unsigned long long& d, unsigned long long a,
                                      unsigned long long b) {
    asm("fma.rn.f32x2 %0, %1, %2, %0;" : "+l"(d) : "l"(a), "l"(b));
}
__device__ __forceinline__ float2 unpack2(unsigned long long v) {
    float2 f;
    asm("mov.b64 {%0, %1}, %2;" : "=f"(f.x), "=f"(f.y) : "l"(v));
    return f;
}

// ---------------- fence-light grid barrier (no CCTL.IVALL, no MEMBAR) -------------
__device__ __forceinline__ void grid_barrier(unsigned target) {
    __syncthreads();
    if (threadIdx.x == 0) {
        unsigned prev;
        asm volatile("atom.acq_rel.gpu.add.u32 %0, [%1], 1;"
                     : "=r"(prev) : "l"(&g_bar_count) : "memory");
        if (prev == target * REC_BLOCKS - 1u) {
            asm volatile("st.release.gpu.u32 [%0], %1;"
                         :: "l"(&g_bar_gen), "r"(target) : "memory");
        } else {
            unsigned g;
            do {
                asm volatile("ld.acquire.gpu.u32 %0, [%1];"
                             : "=r"(g) : "l"(&g_bar_gen) : "memory");
            } while (g < target);
        }
    }
    __syncthreads();
}

// ---------------- prep: pack U/W unit-major, masks, h init (transposed) -----------
__global__ void prep_kernel(const int* __restrict__ x, const float* __restrict__ hidden,
                            const float* __restrict__ Wf, const float* __restrict__ Uf,
                            const float* __restrict__ Wb, const float* __restrict__ Ub) {
    const long long NU = 2LL * UNITS * G3;
    const long long NW = 2LL * EMB * G3;
    const long long NM = 2LL * NT * NB;
    const long long NH = 2LL * NB * UNITS;
    const long long total = NU + NW + NM + NH;
    const long long stride = (long long)gridDim.x * blockDim.x;
    for (long long i = (long long)blockIdx.x * blockDim.x + threadIdx.x; i < total; i += stride) {
        if (i < NU) {
            long long dir = i / ((long long)UNITS * G3);
            long long rem = i - dir * (long long)UNITS * G3;
            int k = (int)(rem / G3);
            int p = (int)(rem % G3);
            const float* U = dir ? Ub : Uf;
            g_U[i] = U[(long long)k * G3 + (p % 3) * UNITS + p / 3];
        } else if (i < NU + NW) {
            long long j = i - NU;
            long long dir = j / ((long long)EMB * G3);
            long long rem = j - dir * (long long)EMB * G3;
            int k = (int)(rem / G3);
            int p = (int)(rem % G3);
            const float* W = dir ? Wb : Wf;
            g_W[j] = W[(long long)k * G3 + (p % 3) * UNITS + p / 3];
        } else if (i < NU + NW + NM) {
            long long j = i - NU - NW;
            int dir = (int)(j / (NT * NB));
            int rem = (int)(j % (NT * NB));
            int s = rem / NB, b = rem % NB;
            int t = dir ? (NT - 1 - s) : s;
            g_mask[dir][s][b] = (x[b * NT + t] != 0) ? 1 : 0;
        } else {
            long long j = i - NU - NW - NM;
            int dir = (int)(j / (NB * UNITS));
            int rem = (int)(j % (NB * UNITS));
            int u = rem / NB, b = rem % NB;
            g_h[dir][0][u][b] = hidden[b * UNITS + u];
        }
    }
    if (blockIdx.x == 0 && threadIdx.x == 0) { g_bar_count = 0u; g_bar_gen = 0u; }
}

// ---------------- gx = gather(emb, x) @ W_packed + b_in (f32x2) -------------------
__global__ __launch_bounds__(256) void gx_kernel(const int* __restrict__ x,
                                                 const float* __restrict__ emb,
                                                 const float* __restrict__ bf_in,
                                                 const float* __restrict__ bb_in) {
    const int ct  = blockIdx.x;
    const int t   = blockIdx.y;
    const int dir = blockIdx.z;
    const int tid = threadIdx.x;
    const int pbase = ct * 64;
    const int tx = tid & 15, ty = tid >> 4;
    const int tx4 = tx << 2, ty4 = ty << 2;

    __shared__ float As[16][68];
    __shared__ float Ws[16][68];
    __shared__ int   toks[64];

    if (tid < 64) {
        int tt = dir ? (NT - 1 - t) : t;
        toks[tid] = x[tid * NT + tt];
    }
    __syncthreads();

    const float* Wsrc = g_W + (size_t)dir * EMB * G3;
    unsigned long long c00 = 0, c01 = 0, c02 = 0, c03 = 0;
    unsigned long long c10 = 0, c11 = 0, c12 = 0, c13 = 0;

    for (int k0 = 0; k0 < EMB; k0 += 16) {
        {
            int r   = tid >> 2;
            int kk4 = (tid & 3) << 2;
            const float4 v = *(const float4*)(emb + (size_t)toks[r] * EMB + k0 + kk4);
            As[kk4 + 0][r] = v.x; As[kk4 + 1][r] = v.y;
            As[kk4 + 2][r] = v.z; As[kk4 + 3][r] = v.w;
        }
        {
            int kk = tid >> 4;
            int p4 = (tid & 15) << 2;
            *(float4*)&Ws[kk][p4] = *(const float4*)(Wsrc + (size_t)(k0 + kk) * G3 + pbase + p4);
        }
        __syncthreads();
#pragma unroll
        for (int kk = 0; kk < 16; kk++) {
            unsigned long long a01 = *(const unsigned long long*)&As[kk][ty4];
            unsigned long long a23 = *(const unsigned long long*)&As[kk][ty4 + 2];
            float4 w = *(const float4*)&Ws[kk][tx4];
            unsigned long long W0 = pack2(w.x), W1 = pack2(w.y);
            unsigned long long W2 = pack2(w.z), W3 = pack2(w.w);
            ffma2(c00, a01, W0); ffma2(c01, a01, W1); ffma2(c02, a01, W2); ffma2(c03, a01, W3);
            ffma2(c10, a23, W0); ffma2(c11, a23, W1); ffma2(c12, a23, W2); ffma2(c13, a23, W3);
        }
        __syncthreads();
    }

    const float* bsrc = dir ? bb_in : bf_in;
    float bin[4];
#pragma unroll
    for (int j = 0; j < 4; j++) {
        int p = pbase + tx4 + j;
        bin[j] = bsrc[(p % 3) * UNITS + p / 3];
    }
    float2 u00 = unpack2(c00), u01 = unpack2(c01), u02 = unpack2(c02), u03 = unpack2(c03);
    float2 u10 = unpack2(c10), u11 = unpack2(c11), u12 = unpack2(c12), u13 = unpack2(c13);
    float rows[4][4] = {
        {u00.x, u01.x, u02.x, u03.x},
        {u00.y, u01.y, u02.y, u03.y},
        {u10.x, u11.x, u12.x, u13.x},
        {u10.y, u11.y, u12.y, u13.y},
    };
    float* gxbase = g_gx + ((size_t)(dir * NT + t) * NB) * G3;
#pragma unroll
    for (int i = 0; i < 4; i++) {
        int b = ty4 + i;
        float4 o = make_float4(rows[i][0] + bin[0], rows[i][1] + bin[1],
                               rows[i][2] + bin[2], rows[i][3] + bin[3]);
        *(float4*)(gxbase + (size_t)b * G3 + pbase + tx4) = o;
    }
}

// ---------------- persistent recurrent kernel + fused final-state GEMM ------------
// 128 blocks = 2 dirs x 64 unit-tiles. U tile (192KB) persistent in smem.
// h staged in KC-chunks, double buffered with register prefetch. f32x2 math.
#define REC_US (48 * UNITS)           // 49152 floats
#define REC_SMEM_BYTES ((REC_US + 2 * KC * NB) * 4)   // 229376 B

__global__ __launch_bounds__(256) void recurrent_kernel(const float* __restrict__ bf_rec,
                                                        const float* __restrict__ bb_rec,
                                                        const float* __restrict__ Wp,
                                                        const float* __restrict__ bp,
                                                        float* __restrict__ out) {
    extern __shared__ float sm[];
    float* us  = sm;                  // [1024][48] U tile
    float* hsA = sm + REC_US;         // [KC][NB]
    float* hsB = hsA + KC * NB;

    const int blk   = blockIdx.x;
    const int dir   = blk >> 6;
    const int utile = blk & 63;
    const int pbase = utile * 48;
    const int ubase = utile * 16;
    const int tid = threadIdx.x;
    const int tx = tid & 15;
    const int ty = tid >> 4;
    const int ty4 = ty << 2;
    const int u  = ubase + tx;

    const float* brec = dir ? bb_rec : bf_rec;
    const float bz = brec[u];
    const float br = brec[UNITS + u];
    const float bh = brec[2 * UNITS + u];

    // ---- load U tile to smem once ----
    {
        const float* Up = g_U + (size_t)dir * UNITS * G3 + pbase;
        for (int i = tid; i < REC_US / 4; i += 256) {
            int k = i / 12, c4 = (i - k * 12) << 2;
            *(float4*)&us[k * 48 + c4] = *(const float4*)(Up + (size_t)k * G3 + c4);
        }
    }
    __syncthreads();

    const float* hbase = &g_h[dir][0][0][0];
    const size_t ppsz  = (size_t)UNITS * NB;

    for (int s = 0; s < NT; s++) {
        const float* hcur = hbase + (size_t)(s & 1) * ppsz;
        float*       hnxt = (float*)hbase + (size_t)((s + 1) & 1) * ppsz;

        // prefetch epilogue operands (used ~25K cycles later)
        const float* gxp = g_gx + ((size_t)(dir * NT + s) * NB) * G3 + pbase + tx * 3;
        float gz[4], gr[4], gh[4];
#pragma unroll
        for (int i = 0; i < 4; i++) {
            const float* gp = gxp + (size_t)(ty4 + i) * G3;
            gz[i] = __ldcs(gp); gr[i] = __ldcs(gp + 1); gh[i] = __ldcs(gp + 2);
        }
        float4 hp4 = __ldcg((const float4*)(hcur + (size_t)u * NB + ty4));
        uchar4 m4 = *(const uchar4*)&g_mask[dir][s][ty4];

        unsigned long long a00 = 0, a01 = 0, a02 = 0, a10 = 0, a11 = 0, a12 = 0;

        // stage chunk 0
        float4 pf[4];
#pragma unroll
        for (int j = 0; j < 4; j++) {
            int f = tid + j * 256;
            int kk = f >> 4, b4 = (f & 15) << 2;
            pf[j] = __ldcg((const float4*)(hcur + (size_t)kk * NB + b4));
        }
#pragma unroll
        for (int j = 0; j < 4; j++) {
            int f = tid + j * 256;
            int kk = f >> 4, b4 = (f & 15) << 2;
            *(float4*)&hsA[kk * NB + b4] = pf[j];
        }
        __syncthreads();

        for (int c = 0; c < UNITS / KC; c++) {
            if (c + 1 < UNITS / KC) {
#pragma unroll
                for (int j = 0; j < 4; j++) {
                    int f = tid + j * 256;
                    int kk = f >> 4, b4 = (f & 15) << 2;
                    pf[j] = __ldcg((const float4*)(hcur + (size_t)((c + 1) * KC + kk) * NB + b4));
                }
            }
            const float* hb = (c & 1) ? hsB : hsA;
            const float* ur = us + c * KC * 48 + tx * 3;
#pragma unroll 8
            for (int kk = 0; kk < KC; kk++) {
                unsigned long long h01 = *(const unsigned long long*)(hb + kk * NB + ty4);
                unsigned long long h23 = *(const unsigned long long*)(hb + kk * NB + ty4 + 2);
                unsigned long long U0 = pack2(ur[0]);
                unsigned long long U1 = pack2(ur[1]);
                unsigned long long U2 = pack2(ur[2]);
                ffma2(a00, h01, U0); ffma2(a01, h01, U1); ffma2(a02, h01, U2);
                ffma2(a10, h23, U0); ffma2(a11, h23, U1); ffma2(a12, h23, U2);
                ur += 48;
            }
            if (c + 1 < UNITS / KC) {
                float* hw = ((c + 1) & 1) ? hsB : hsA;
#pragma unroll
                for (int j = 0; j < 4; j++) {
                    int f = tid + j * 256;
                    int kk = f >> 4, b4 = (f & 15) << 2;
                    *(float4*)&hw[kk * NB + b4] = pf[j];
                }
            }
            __syncthreads();
        }

        // ---- GRU update ----
        float2 z01 = unpack2(a00), r01 = unpack2(a01), q01 = unpack2(a02);
        float2 z23 = unpack2(a10), r23 = unpack2(a11), q23 = unpack2(a12);
        float az[4] = {z01.x, z01.y, z23.x, z23.y};
        float ar[4] = {r01.x, r01.y, r23.x, r23.y};
        float ah[4] = {q01.x, q01.y, q23.x, q23.y};
        float hpv[4] = {hp4.x, hp4.y, hp4.z, hp4.w};
        unsigned char mv[4] = {m4.x, m4.y, m4.z, m4.w};
        const int tt = dir ? (NT - 1 - s) : s;
        float4 hn4;
        float* hno = (float*)&hn4;
#pragma unroll
        for (int i = 0; i < 4; i++) {
            float z  = 1.f / (1.f + expf(-(gz[i] + az[i] + bz)));
            float r  = 1.f / (1.f + expf(-(gr[i] + ar[i] + br)));
            float hh = tanhf(gh[i] + r * (ah[i] + bh));
            float hn = z * hpv[i] + (1.f - z) * hh;
            if (!mv[i]) hn = hpv[i];
            hno[i] = hn;
            out[((size_t)(ty4 + i) * NT + tt) * (2 * UNITS) + dir * UNITS + u] = hn;
        }
        *(float4*)(hnxt + (size_t)u * NB + ty4) = hn4;

        grid_barrier((unsigned)(s + 1));
    }

    // ---- fused final state: tanh(concat(hf,hb) @ Wp + bp) ----
    // Final h in pingpong buffer 0 (NT even). All blocks synced by last barrier.
    {
        float* sst = sm;                  // reuse U region: [128][NB] staging
        const int tx8 = tid & 7;
        const int tyS = tid >> 3;         // 0..31, 2 batch rows each
        const int ocol = blk * 8 + tx8;   // 128 blocks x 8 = 1024 output cols
        const float* wp = Wp + ocol;
        unsigned long long acc = 0;
        for (int k0 = 0; k0 < 2 * UNITS; k0 += 128) {
            __syncthreads();
#pragma unroll
            for (int j = 0; j < 8; j++) {
                int f = tid + j * 256;
                int kk = f >> 4, b4 = (f & 15) << 2;
                int k = k0 + kk;
                float4 v = __ldcg((const float4*)(&g_h[k >> 10][0][k & 1023][b4]));
                *(float4*)&sst[kk * NB + b4] = v;
            }
            __syncthreads();
#pragma unroll 8
            for (int kk = 0; kk < 128; kk++) {
                float w = __ldg(wp + (size_t)(k0 + kk) * UNITS);
                unsigned long long wv = pack2(w);
                unsigned long long hh = *(const unsigned long long*)(sst + kk * NB + tyS * 2);
                ffma2(acc, hh, wv);
            }
        }
        float2 aa = unpack2(acc);
        float bpv = bp[ocol];
        const size_t so = (size_t)NB * NT * (2 * UNITS);
        out[so + (size_t)(tyS * 2 + 0) * UNITS + ocol] = tanhf(aa.x + bpv);
        out[so + (size_t)(tyS * 2 + 1) * UNITS + ocol] = tanhf(aa.y + bpv);
    }
}

// ---------------- launch ----------------------------------------------------------
extern "C" void kernel_launch(void* const* d_in, const int* in_sizes, int n_in,
                              void* d_out, int out_size) {
    (void)in_sizes; (void)n_in; (void)out_size;
    const int*   x      = (const int*)  d_in[0];
    const float* hidden = (const float*)d_in[1];
    const float* emb    = (const float*)d_in[2];
    const float* Wf     = (const float*)d_in[3];
    const float* Uf     = (const float*)d_in[4];
    const float* bf_in  = (const float*)d_in[5];
    const float* bf_rec = (const float*)d_in[6];
    const float* Wb     = (const float*)d_in[7];
    const float* Ub     = (const float*)d_in[8];
    const float* bb_in  = (const float*)d_in[9];
    const float* bb_rec = (const float*)d_in[10];
    const float* Wp     = (const float*)d_in[11];
    const float* bp     = (const float*)d_in[12];
    float* out = (float*)d_out;

    cudaFuncSetAttribute(recurrent_kernel,
                         cudaFuncAttributeMaxDynamicSharedMemorySize, REC_SMEM_BYTES);

    prep_kernel<<<4096, 256>>>(x, hidden, Wf, Uf, Wb, Ub);
    dim3 ggx(G3 / 64, NT, 2);
    gx_kernel<<<ggx, 256>>>(x, emb, bf_in, bb_in);
    recurrent_kernel<<<REC_BLOCKS, 256, REC_SMEM_BYTES>>>(bf_rec, bb_rec, Wp, bp, out);
}